// round 5
// baseline (speedup 1.0000x reference)
#include <cuda_runtime.h>
#include <cuda_bf16.h>

// ---------------------------------------------------------------------------
// SelfAttention_50500225466674
// out = -(1/beta) * sum_{h,q} logsumexp_k( beta * (x Wq^T)[q,h,:] . (x Wk^T)[k,h,:] )
// N=2048, D=128, H=32, Z=64, beta = 1/sqrt(128)
// Stage 1: bf16 HMMA projection  Q[h][n][z], K[h][n][z]  (Q pre-scaled by beta*log2e)
// Stage 2: fused per-(h,qtile) score GEMM + online base-2 logsumexp
// Stage 3: deterministic reduction of 512 CTA partials
// ---------------------------------------------------------------------------

#define NTOK 2048
#define DIM  128
#define NH   32
#define ZD   64

static __device__ __nv_bfloat16 g_Q[(size_t)NH * NTOK * ZD];   // 8 MB
static __device__ __nv_bfloat16 g_K[(size_t)NH * NTOK * ZD];   // 8 MB
static __device__ float g_partial[16 * NH];                     // 512 CTA partials

// ---------------- PTX helpers ----------------
__device__ __forceinline__ void ldsm4(unsigned addr, unsigned &r0, unsigned &r1,
                                      unsigned &r2, unsigned &r3) {
    asm volatile("ldmatrix.sync.aligned.m8n8.x4.shared.b16 {%0,%1,%2,%3}, [%4];"
                 : "=r"(r0), "=r"(r1), "=r"(r2), "=r"(r3)
                 : "r"(addr));
}

__device__ __forceinline__ void mma_bf16(float *c, unsigned a0, unsigned a1,
                                         unsigned a2, unsigned a3,
                                         unsigned b0, unsigned b1) {
    asm volatile(
        "mma.sync.aligned.m16n8k16.row.col.f32.bf16.bf16.f32 "
        "{%0,%1,%2,%3}, {%4,%5,%6,%7}, {%8,%9}, {%0,%1,%2,%3};"
        : "+f"(c[0]), "+f"(c[1]), "+f"(c[2]), "+f"(c[3])
        : "r"(a0), "r"(a1), "r"(a2), "r"(a3), "r"(b0), "r"(b1));
}

__device__ __forceinline__ float ex2f(float x) {
    float y; asm("ex2.approx.f32 %0, %1;" : "=f"(y) : "f"(x)); return y;
}
__device__ __forceinline__ float lg2f(float x) {
    float y; asm("lg2.approx.f32 %0, %1;" : "=f"(y) : "f"(x)); return y;
}
__device__ __forceinline__ unsigned smem_u32(const void *p) {
    return (unsigned)__cvta_generic_to_shared(p);
}
__device__ __forceinline__ unsigned pack_bf2(float a, float b) {
    __nv_bfloat162 h = __floats2bfloat162_rn(a, b);
    return *reinterpret_cast<unsigned *>(&h);
}

// ---------------------------------------------------------------------------
// Stage 1: projection. grid (16 n-tiles, 32 heads, 2 {Q,K}), 256 threads.
// C[128n x 64z] = x_tile[128 x 128] @ W[h]^T, fp32 -> bf16 inputs, fp32 accum.
// Dynamic smem: sX 128x128 bf16 (32KB) + sW 64x128 bf16 (16KB) = 48KB, XOR swizzle.
// ---------------------------------------------------------------------------
__global__ void __launch_bounds__(256)
proj_kernel(const float *__restrict__ x, const float *__restrict__ Wq,
            const float *__restrict__ Wk) {
    extern __shared__ uint4 smem[];
    uint4 *sX4 = smem;              // 128 rows x 16 chunks(16B)
    uint4 *sW4 = smem + 128 * 16;   // 64 rows x 16 chunks

    const int tid = threadIdx.x, lane = tid & 31, w = tid >> 5;
    const int nb = blockIdx.x * 128, h = blockIdx.y, isK = blockIdx.z;
    const float *W = (isK ? Wk : Wq) + (size_t)h * ZD * DIM;
    __nv_bfloat16 *gout = (isK ? g_K : g_Q) + ((size_t)h * NTOK + nb) * ZD;

    // load x tile (fp32 -> bf16, swizzled)
    for (int i = tid; i < 2048; i += 256) {
        int row = i >> 4, c = i & 15;
        const float4 *gp =
            reinterpret_cast<const float4 *>(x + (size_t)(nb + row) * DIM + c * 8);
        float4 f0 = gp[0], f1 = gp[1];
        uint4 v;
        v.x = pack_bf2(f0.x, f0.y); v.y = pack_bf2(f0.z, f0.w);
        v.z = pack_bf2(f1.x, f1.y); v.w = pack_bf2(f1.z, f1.w);
        sX4[row * 16 + (c ^ (row & 7))] = v;
    }
    // load W tile
    for (int i = tid; i < 1024; i += 256) {
        int row = i >> 4, c = i & 15;
        const float4 *gp =
            reinterpret_cast<const float4 *>(W + (size_t)row * DIM + c * 8);
        float4 f0 = gp[0], f1 = gp[1];
        uint4 v;
        v.x = pack_bf2(f0.x, f0.y); v.y = pack_bf2(f0.z, f0.w);
        v.z = pack_bf2(f1.x, f1.y); v.w = pack_bf2(f1.z, f1.w);
        sW4[row * 16 + (c ^ (row & 7))] = v;
    }
    __syncthreads();

    const int wm = w >> 1, wn = w & 1;   // 4 warps along m(128), 2 along n(64)
    float acc[2][4][4];
#pragma unroll
    for (int i = 0; i < 2; i++)
#pragma unroll
        for (int j = 0; j < 4; j++)
#pragma unroll
            for (int k = 0; k < 4; k++) acc[i][j][k] = 0.f;

    unsigned sXb = smem_u32(sX4), sWb = smem_u32(sW4);
    const int arow0 = wm * 32 + (lane & 15);
    const int brow_off = (lane & 7) + ((lane >> 4) & 1) * 8;
    const int bco = (lane >> 3) & 1;

#pragma unroll
    for (int kk = 0; kk < 8; kk++) {   // K = 128, 16 per step
        unsigned a[2][4];
#pragma unroll
        for (int i = 0; i < 2; i++) {
            int r = arow0 + i * 16;
            int ch = (kk * 2 + (lane >> 4)) ^ (r & 7);
            ldsm4(sXb + (unsigned)((r * 16 + ch) * 16), a[i][0], a[i][1], a[i][2], a[i][3]);
        }
#pragma unroll
        for (int g = 0; g < 2; g++) {
            int brow = wn * 32 + g * 16 + brow_off;
            int bch = (kk * 2 + bco) ^ (brow & 7);
            unsigned b0, b1, b2, b3;
            ldsm4(sWb + (unsigned)((brow * 16 + bch) * 16), b0, b1, b2, b3);
#pragma unroll
            for (int i = 0; i < 2; i++) {
                mma_bf16(acc[i][g * 2],     a[i][0], a[i][1], a[i][2], a[i][3], b0, b1);
                mma_bf16(acc[i][g * 2 + 1], a[i][0], a[i][1], a[i][2], a[i][3], b2, b3);
            }
        }
    }

    // Q gets beta*log2e folded in; K stays raw.
    const float scale = isK ? 1.0f : (float)(1.4426950408889634 / 11.313708498984760390);

#pragma unroll
    for (int i = 0; i < 2; i++) {
        int r = wm * 32 + i * 16 + (lane >> 2);
#pragma unroll
        for (int j = 0; j < 4; j++) {
            int cb = wn * 32 + j * 8 + 2 * (lane & 3);
            __nv_bfloat162 lo = __floats2bfloat162_rn(acc[i][j][0] * scale, acc[i][j][1] * scale);
            __nv_bfloat162 hi = __floats2bfloat162_rn(acc[i][j][2] * scale, acc[i][j][3] * scale);
            *reinterpret_cast<__nv_bfloat162 *>(gout + (size_t)r * ZD + cb) = lo;
            *reinterpret_cast<__nv_bfloat162 *>(gout + (size_t)(r + 8) * ZD + cb) = hi;
        }
    }
}

// ---------------------------------------------------------------------------
// Stage 2: fused scores + online base-2 logsumexp.
// grid (16 q-tiles, 32 heads), 256 threads (8 warps; warp w = q rows 16w..16w+15).
// Scores are already in base-2 logit units (scale baked into Q).
// ---------------------------------------------------------------------------
__global__ void __launch_bounds__(256)
attn_lse_kernel() {
    __shared__ uint4 sQ4[128 * 8];   // 128 rows x 64 bf16 (8 x 16B chunks), swizzled
    __shared__ uint4 sK4[128 * 8];
    __shared__ float warpSum[8];

    const int tid = threadIdx.x, lane = tid & 31, w = tid >> 5;
    const int h = blockIdx.y, qt = blockIdx.x;
    const __nv_bfloat16 *gq = g_Q + ((size_t)h * NTOK + (size_t)qt * 128) * ZD;
    const __nv_bfloat16 *gk = g_K + (size_t)h * NTOK * ZD;

    // load Q tile once
    for (int i = tid; i < 1024; i += 256) {
        int row = i >> 3, c = i & 7;
        uint4 v = *reinterpret_cast<const uint4 *>(gq + (size_t)row * ZD + c * 8);
        sQ4[row * 8 + (c ^ (row & 7))] = v;
    }

    float m0 = -INFINITY, s0 = 0.f, m1 = -INFINITY, s1 = 0.f;
    const unsigned sQb = smem_u32(sQ4), sKb = smem_u32(sK4);
    const int arow = 16 * w + (lane & 15);
    const int brow_off = (lane & 7) + ((lane >> 4) & 1) * 8;
    const int bco = (lane >> 3) & 1;

#pragma unroll 1
    for (int kt = 0; kt < 16; kt++) {
        __syncthreads();   // previous tile's smem reads finished
        const __nv_bfloat16 *gkt = gk + (size_t)kt * 128 * ZD;
        for (int i = tid; i < 1024; i += 256) {
            int row = i >> 3, c = i & 7;
            uint4 v = *reinterpret_cast<const uint4 *>(gkt + (size_t)row * ZD + c * 8);
            sK4[row * 8 + (c ^ (row & 7))] = v;
        }
        __syncthreads();

        float acc[16][4];
#pragma unroll
        for (int j = 0; j < 16; j++) {
            acc[j][0] = 0.f; acc[j][1] = 0.f; acc[j][2] = 0.f; acc[j][3] = 0.f;
        }

#pragma unroll
        for (int kk = 0; kk < 4; kk++) {   // Z = 64, 16 per step
            unsigned a0, a1, a2, a3;
            int ach = (kk * 2 + (lane >> 4)) ^ (arow & 7);
            ldsm4(sQb + (unsigned)((arow * 8 + ach) * 16), a0, a1, a2, a3);
#pragma unroll
            for (int n16 = 0; n16 < 8; n16++) {
                int brow = n16 * 16 + brow_off;
                int bch = (kk * 2 + bco) ^ (brow & 7);
                unsigned b0, b1, b2, b3;
                ldsm4(sKb + (unsigned)((brow * 8 + bch) * 16), b0, b1, b2, b3);
                mma_bf16(acc[n16 * 2],     a0, a1, a2, a3, b0, b1);
                mma_bf16(acc[n16 * 2 + 1], a0, a1, a2, a3, b2, b3);
            }
        }

        // online lse over this thread's 32 cols of row r0=lane>>2 (+8)
        float t0a = -INFINITY, t0b = -INFINITY, t1a = -INFINITY, t1b = -INFINITY;
#pragma unroll
        for (int j = 0; j < 16; j++) {
            t0a = fmaxf(t0a, acc[j][0]); t0b = fmaxf(t0b, acc[j][1]);
            t1a = fmaxf(t1a, acc[j][2]); t1b = fmaxf(t1b, acc[j][3]);
        }
        float mn0 = fmaxf(m0, fmaxf(t0a, t0b));
        float mn1 = fmaxf(m1, fmaxf(t1a, t1b));
        s0 *= ex2f(m0 - mn0);   // 0 * 0 = 0 on first tile (m0 = -inf)
        s1 *= ex2f(m1 - mn1);
        float p0 = 0.f, p1 = 0.f, p2 = 0.f, p3 = 0.f;
#pragma unroll
        for (int j = 0; j < 16; j++) {
            p0 += ex2f(acc[j][0] - mn0);
            p1 += ex2f(acc[j][1] - mn0);
            p2 += ex2f(acc[j][2] - mn1);
            p3 += ex2f(acc[j][3] - mn1);
        }
        s0 += p0 + p1; s1 += p2 + p3;
        m0 = mn0; m1 = mn1;
    }

    // merge (m,s) across the 4 lanes of each quad (full 128-col rows)
#pragma unroll
    for (int off = 1; off <= 2; off <<= 1) {
        float mo = __shfl_xor_sync(0xffffffffu, m0, off);
        float so = __shfl_xor_sync(0xffffffffu, s0, off);
        float mn = fmaxf(m0, mo);
        s0 = s0 * ex2f(m0 - mn) + so * ex2f(mo - mn);
        m0 = mn;
        mo = __shfl_xor_sync(0xffffffffu, m1, off);
        so = __shfl_xor_sync(0xffffffffu, s1, off);
        mn = fmaxf(m1, mo);
        s1 = s1 * ex2f(m1 - mn) + so * ex2f(mo - mn);
        m1 = mn;
    }

    float contrib = 0.f;
    if ((lane & 3) == 0) contrib = (m0 + lg2f(s0)) + (m1 + lg2f(s1));
#pragma unroll
    for (int off = 16; off; off >>= 1)
        contrib += __shfl_xor_sync(0xffffffffu, contrib, off);
    if (lane == 0) warpSum[w] = contrib;
    __syncthreads();
    if (tid == 0) {
        float t = 0.f;
#pragma unroll
        for (int i = 0; i < 8; i++) t += warpSum[i];
        g_partial[blockIdx.y * 16 + blockIdx.x] = t;   // deterministic, no atomics
    }
}

// ---------------------------------------------------------------------------
// Stage 3: deterministic reduction of 512 partials; out = -sqrt(128)*ln2 * sum
// ---------------------------------------------------------------------------
__global__ void finalize_kernel(float *out) {
    __shared__ float red[256];
    int t = threadIdx.x;
    float s = g_partial[t] + g_partial[t + 256];
    red[t] = s;
    __syncthreads();
    for (int st = 128; st > 0; st >>= 1) {
        if (t < st) red[t] += red[t + st];
        __syncthreads();
    }
    if (t == 0) {
        const double C = -(11.313708498984760390 * 0.69314718055994530942);
        out[0] = (float)(C * (double)red[0]);
    }
}

// ---------------------------------------------------------------------------
extern "C" void kernel_launch(void *const *d_in, const int *in_sizes, int n_in,
                              void *d_out, int out_size) {
    (void)in_sizes; (void)n_in; (void)out_size;
    const float *x  = (const float *)d_in[0];
    const float *Wq = (const float *)d_in[1];
    const float *Wk = (const float *)d_in[2];
    float *out = (float *)d_out;

    // 48KB dynamic smem (exactly the default cap; attribute set defensively)
    static bool attr_set = false;
    if (!attr_set) {
        cudaFuncSetAttribute(proj_kernel, cudaFuncAttributeMaxDynamicSharedMemorySize, 49152);
        attr_set = true;
    }

    proj_kernel<<<dim3(16, 32, 2), 256, 49152>>>(x, Wq, Wk);
    attn_lse_kernel<<<dim3(16, 32), 256>>>();
    finalize_kernel<<<1, 256>>>(out);
}

// round 6
// speedup vs baseline: 1.1725x; 1.1725x over previous
#include <cuda_runtime.h>
#include <cuda_bf16.h>
#include <cuda_fp16.h>

// ---------------------------------------------------------------------------
// SelfAttention_50500225466674
// out = -(1/beta) * sum_{h,q} logsumexp_k( beta * (x Wq^T)[q,h,:] . (x Wk^T)[k,h,:] )
// N=2048, D=128, H=32, Z=64, beta = 1/sqrt(128)
// Stage 1: bf16 HMMA projection (2 heads/CTA), Q pre-scaled by beta*log2e
// Stage 2: fused score GEMM (m32/warp) + online base-2 lse, f16x2 epilogue,
//          cp.async double-buffered K tiles
// Stage 3: deterministic reduction of 512 CTA partials
// ---------------------------------------------------------------------------

#define NTOK 2048
#define DIM  128
#define NH   32
#define ZD   64

static __device__ __nv_bfloat16 g_Q[(size_t)NH * NTOK * ZD];   // 8 MB
static __device__ __nv_bfloat16 g_K[(size_t)NH * NTOK * ZD];   // 8 MB
static __device__ float g_partial[16 * NH];                     // 512 partials

// ---------------- PTX helpers ----------------
__device__ __forceinline__ void ldsm4(unsigned addr, unsigned &r0, unsigned &r1,
                                      unsigned &r2, unsigned &r3) {
    asm volatile("ldmatrix.sync.aligned.m8n8.x4.shared.b16 {%0,%1,%2,%3}, [%4];"
                 : "=r"(r0), "=r"(r1), "=r"(r2), "=r"(r3)
                 : "r"(addr));
}

__device__ __forceinline__ void mma_bf16(float *c, unsigned a0, unsigned a1,
                                         unsigned a2, unsigned a3,
                                         unsigned b0, unsigned b1) {
    asm volatile(
        "mma.sync.aligned.m16n8k16.row.col.f32.bf16.bf16.f32 "
        "{%0,%1,%2,%3}, {%4,%5,%6,%7}, {%8,%9}, {%0,%1,%2,%3};"
        : "+f"(c[0]), "+f"(c[1]), "+f"(c[2]), "+f"(c[3])
        : "r"(a0), "r"(a1), "r"(a2), "r"(a3), "r"(b0), "r"(b1));
}

__device__ __forceinline__ float ex2f(float x) {
    float y; asm("ex2.approx.f32 %0, %1;" : "=f"(y) : "f"(x)); return y;
}
__device__ __forceinline__ float lg2f(float x) {
    float y; asm("lg2.approx.f32 %0, %1;" : "=f"(y) : "f"(x)); return y;
}
__device__ __forceinline__ __half2 h2ex2(__half2 x) {
    unsigned xu = *reinterpret_cast<unsigned *>(&x), yu;
    asm("ex2.approx.f16x2 %0, %1;" : "=r"(yu) : "r"(xu));
    return *reinterpret_cast<__half2 *>(&yu);
}
__device__ __forceinline__ unsigned smem_u32(const void *p) {
    return (unsigned)__cvta_generic_to_shared(p);
}
__device__ __forceinline__ unsigned pack_bf2(float a, float b) {
    __nv_bfloat162 h = __floats2bfloat162_rn(a, b);
    return *reinterpret_cast<unsigned *>(&h);
}
__device__ __forceinline__ void cp16(void *sdst, const void *gsrc) {
    unsigned d = smem_u32(sdst);
    asm volatile("cp.async.cg.shared.global [%0], [%1], 16;" :: "r"(d), "l"(gsrc) : "memory");
}
#define CP_COMMIT() asm volatile("cp.async.commit_group;" ::: "memory")
#define CP_WAIT(n)  asm volatile("cp.async.wait_group %0;" :: "n"(n) : "memory")

// ---------------------------------------------------------------------------
// Stage 1: projection, 2 heads per CTA. grid (16 n-tiles, 16 head-pairs, 2 {Q,K}),
// 256 threads. Per head: C[128n x 64z] = x_tile[128x128] @ W[h]^T.
// smem: sX 32KB + sW 2x16KB = 64KB dynamic, XOR swizzle.
// ---------------------------------------------------------------------------
__global__ void __launch_bounds__(256)
proj_kernel(const float *__restrict__ x, const float *__restrict__ Wq,
            const float *__restrict__ Wk) {
    extern __shared__ uint4 smem[];
    uint4 *sX4 = smem;              // 128 rows x 16 chunks(16B)
    uint4 *sW4 = smem + 128 * 16;   // 2 x (64 rows x 16 chunks)

    const int tid = threadIdx.x, lane = tid & 31, w = tid >> 5;
    const int nb = blockIdx.x * 128, isK = blockIdx.z;
    const int h0 = blockIdx.y * 2;
    const float *Wbase = (isK ? Wk : Wq);

    // x tile (fp32 -> bf16, swizzled)
    for (int i = tid; i < 2048; i += 256) {
        int row = i >> 4, c = i & 15;
        const float4 *gp =
            reinterpret_cast<const float4 *>(x + (size_t)(nb + row) * DIM + c * 8);
        float4 f0 = gp[0], f1 = gp[1];
        uint4 v;
        v.x = pack_bf2(f0.x, f0.y); v.y = pack_bf2(f0.z, f0.w);
        v.z = pack_bf2(f1.x, f1.y); v.w = pack_bf2(f1.z, f1.w);
        sX4[row * 16 + (c ^ (row & 7))] = v;
    }
    // both heads' W tiles
    for (int i = tid; i < 2048; i += 256) {
        int hh = i >> 10, r = (i >> 4) & 63, c = i & 15;
        const float *W = Wbase + (size_t)(h0 + hh) * ZD * DIM;
        const float4 *gp = reinterpret_cast<const float4 *>(W + (size_t)r * DIM + c * 8);
        float4 f0 = gp[0], f1 = gp[1];
        uint4 v;
        v.x = pack_bf2(f0.x, f0.y); v.y = pack_bf2(f0.z, f0.w);
        v.z = pack_bf2(f1.x, f1.y); v.w = pack_bf2(f1.z, f1.w);
        sW4[hh * 1024 + r * 16 + (c ^ (r & 7))] = v;
    }
    __syncthreads();

    const int wm = w >> 1, wn = w & 1;   // 4 warps along m(128), 2 along z(64)
    const unsigned sXb = smem_u32(sX4);
    const int arow0 = wm * 32 + (lane & 15);
    const int brow_off = (lane & 7) + ((lane >> 4) & 1) * 8;
    const int bco = (lane >> 3) & 1;
    const float scale = isK ? 1.0f : (float)(1.4426950408889634 / 11.313708498984760390);

    for (int hh = 0; hh < 2; hh++) {
        const unsigned sWb = smem_u32(sW4 + hh * 1024);
        float acc[2][4][4];
#pragma unroll
        for (int i = 0; i < 2; i++)
#pragma unroll
            for (int j = 0; j < 4; j++)
#pragma unroll
                for (int k = 0; k < 4; k++) acc[i][j][k] = 0.f;

#pragma unroll
        for (int kk = 0; kk < 8; kk++) {   // K = 128
            unsigned a[2][4];
#pragma unroll
            for (int i = 0; i < 2; i++) {
                int r = arow0 + i * 16;
                int ch = (kk * 2 + (lane >> 4)) ^ (r & 7);
                ldsm4(sXb + (unsigned)((r * 16 + ch) * 16), a[i][0], a[i][1], a[i][2], a[i][3]);
            }
#pragma unroll
            for (int g = 0; g < 2; g++) {
                int brow = wn * 32 + g * 16 + brow_off;
                int bch = (kk * 2 + bco) ^ (brow & 7);
                unsigned b0, b1, b2, b3;
                ldsm4(sWb + (unsigned)((brow * 16 + bch) * 16), b0, b1, b2, b3);
#pragma unroll
                for (int i = 0; i < 2; i++) {
                    mma_bf16(acc[i][g * 2],     a[i][0], a[i][1], a[i][2], a[i][3], b0, b1);
                    mma_bf16(acc[i][g * 2 + 1], a[i][0], a[i][1], a[i][2], a[i][3], b2, b3);
                }
            }
        }

        __nv_bfloat16 *gout =
            (isK ? g_K : g_Q) + ((size_t)(h0 + hh) * NTOK + nb) * ZD;
#pragma unroll
        for (int i = 0; i < 2; i++) {
            int r = wm * 32 + i * 16 + (lane >> 2);
#pragma unroll
            for (int j = 0; j < 4; j++) {
                int cb = wn * 32 + j * 8 + 2 * (lane & 3);
                __nv_bfloat162 lo = __floats2bfloat162_rn(acc[i][j][0] * scale, acc[i][j][1] * scale);
                __nv_bfloat162 hi = __floats2bfloat162_rn(acc[i][j][2] * scale, acc[i][j][3] * scale);
                *reinterpret_cast<__nv_bfloat162 *>(gout + (size_t)r * ZD + cb) = lo;
                *reinterpret_cast<__nv_bfloat162 *>(gout + (size_t)(r + 8) * ZD + cb) = hi;
            }
        }
    }
}

// ---------------------------------------------------------------------------
// Stage 2: fused scores + online base-2 lse.
// grid (16 q-tiles, 32 heads), 128 threads (4 warps; warp w = q rows 32w..32w+31).
// smem (dynamic 48KB): sQ 16KB + sK double-buffer 2x16KB. cp.async pipeline.
// Scores already in base-2 logit units (scale baked into Q by stage 1).
// ---------------------------------------------------------------------------
__global__ void __launch_bounds__(128, 2)
attn_lse_kernel() {
    extern __shared__ uint4 dynsmem[];
    uint4 *sQ4 = dynsmem;            // 128 rows x 8 chunks(16B), swizzled
    uint4 *sK4 = dynsmem + 128 * 8;  // 2 x (128 x 8)
    __shared__ float warpSum[4];

    const int tid = threadIdx.x, lane = tid & 31, w = tid >> 5;
    const int h = blockIdx.y, qt = blockIdx.x;
    const __nv_bfloat16 *gq = g_Q + ((size_t)h * NTOK + (size_t)qt * 128) * ZD;
    const __nv_bfloat16 *gk = g_K + (size_t)h * NTOK * ZD;

    // group 0: Q tile + K tile 0
    for (int i = tid; i < 1024; i += 128) {
        int row = i >> 3, c = i & 7;
        cp16(&sQ4[row * 8 + (c ^ (row & 7))], gq + (size_t)row * ZD + c * 8);
    }
    for (int i = tid; i < 1024; i += 128) {
        int row = i >> 3, c = i & 7;
        cp16(&sK4[row * 8 + (c ^ (row & 7))], gk + (size_t)row * ZD + c * 8);
    }
    CP_COMMIT();

    float m[4], s[4];
#pragma unroll
    for (int i = 0; i < 4; i++) { m[i] = -INFINITY; s[i] = 0.f; }

    const unsigned sQb = smem_u32(sQ4);
    const int brow_off = (lane & 7) + ((lane >> 4) & 1) * 8;
    const int bco = (lane >> 3) & 1;

#pragma unroll 1
    for (int kt = 0; kt < 16; kt++) {
        if (kt + 1 < 16) {
            const __nv_bfloat16 *gkt = gk + (size_t)(kt + 1) * 128 * ZD;
            uint4 *buf = sK4 + ((kt + 1) & 1) * 1024;
            for (int i = tid; i < 1024; i += 128) {
                int row = i >> 3, c = i & 7;
                cp16(&buf[row * 8 + (c ^ (row & 7))], gkt + (size_t)row * ZD + c * 8);
            }
            CP_COMMIT();
            CP_WAIT(1);
        } else {
            CP_WAIT(0);
        }
        __syncthreads();

        const unsigned sKb = smem_u32(sK4 + (kt & 1) * 1024);
        float acc[2][16][4];
#pragma unroll
        for (int i = 0; i < 2; i++)
#pragma unroll
            for (int j = 0; j < 16; j++)
#pragma unroll
                for (int k = 0; k < 4; k++) acc[i][j][k] = 0.f;

#pragma unroll
        for (int kk = 0; kk < 4; kk++) {   // Z = 64
            unsigned a[2][4];
#pragma unroll
            for (int i = 0; i < 2; i++) {
                int r = 32 * w + 16 * i + (lane & 15);
                int ch = (kk * 2 + (lane >> 4)) ^ (r & 7);
                ldsm4(sQb + (unsigned)((r * 8 + ch) * 16), a[i][0], a[i][1], a[i][2], a[i][3]);
            }
#pragma unroll
            for (int n16 = 0; n16 < 8; n16++) {
                int brow = n16 * 16 + brow_off;
                int bch = (kk * 2 + bco) ^ (brow & 7);
                unsigned b0, b1, b2, b3;
                ldsm4(sKb + (unsigned)((brow * 8 + bch) * 16), b0, b1, b2, b3);
#pragma unroll
                for (int i = 0; i < 2; i++) {
                    mma_bf16(acc[i][n16 * 2],     a[i][0], a[i][1], a[i][2], a[i][3], b0, b1);
                    mma_bf16(acc[i][n16 * 2 + 1], a[i][0], a[i][1], a[i][2], a[i][3], b2, b3);
                }
            }
        }
        __syncthreads();   // all warps done reading this K buffer

        // f16x2 epilogue: 4 row-slices per thread (i in {0,1}, hh in {0,1})
#pragma unroll
        for (int i = 0; i < 2; i++) {
#pragma unroll
            for (int hh = 0; hh < 2; hh++) {
                const int idx = i * 2 + hh;
                __half2 hv[16];
#pragma unroll
                for (int j = 0; j < 16; j++)
                    hv[j] = __floats2half2_rn(acc[i][j][2 * hh], acc[i][j][2 * hh + 1]);
                __half2 mx[8];
#pragma unroll
                for (int j = 0; j < 8; j++) mx[j] = __hmax2(hv[j], hv[j + 8]);
#pragma unroll
                for (int j = 0; j < 4; j++) mx[j] = __hmax2(mx[j], mx[j + 4]);
                mx[0] = __hmax2(__hmax2(mx[0], mx[1]), __hmax2(mx[2], mx[3]));
                float tmax = fmaxf(__low2float(mx[0]), __high2float(mx[0]));

                float mn = fmaxf(m[idx], tmax);
                s[idx] *= ex2f(m[idx] - mn);
                m[idx] = mn;
                __half2 mn2 = __float2half2_rn(mn);
                __half2 a0 = __float2half2_rn(0.f), a1 = a0, a2 = a0, a3 = a0;
#pragma unroll
                for (int j = 0; j < 16; j += 4) {
                    a0 = __hadd2(a0, h2ex2(__hsub2(hv[j],     mn2)));
                    a1 = __hadd2(a1, h2ex2(__hsub2(hv[j + 1], mn2)));
                    a2 = __hadd2(a2, h2ex2(__hsub2(hv[j + 2], mn2)));
                    a3 = __hadd2(a3, h2ex2(__hsub2(hv[j + 3], mn2)));
                }
                a0 = __hadd2(__hadd2(a0, a1), __hadd2(a2, a3));
                s[idx] += __low2float(a0) + __high2float(a0);
            }
        }
    }

    // merge (m,s) across the 4 lanes of each quad (each slice = one full row)
    float contrib = 0.f;
#pragma unroll
    for (int idx = 0; idx < 4; idx++) {
        float mm = m[idx], ss = s[idx];
#pragma unroll
        for (int off = 1; off <= 2; off <<= 1) {
            float mo = __shfl_xor_sync(0xffffffffu, mm, off);
            float so = __shfl_xor_sync(0xffffffffu, ss, off);
            float mn = fmaxf(mm, mo);
            ss = ss * ex2f(mm - mn) + so * ex2f(mo - mn);
            mm = mn;
        }
        contrib += mm + lg2f(ss);
    }
    if (lane & 3) contrib = 0.f;
#pragma unroll
    for (int off = 16; off; off >>= 1)
        contrib += __shfl_xor_sync(0xffffffffu, contrib, off);
    if (lane == 0) warpSum[w] = contrib;
    __syncthreads();
    if (tid == 0)
        g_partial[blockIdx.y * 16 + blockIdx.x] =
            warpSum[0] + warpSum[1] + warpSum[2] + warpSum[3];
}

// ---------------------------------------------------------------------------
// Stage 3: deterministic reduction; out = -sqrt(128)*ln2 * sum(base-2 lse)
// ---------------------------------------------------------------------------
__global__ void finalize_kernel(float *out) {
    __shared__ float red[256];
    int t = threadIdx.x;
    red[t] = g_partial[t] + g_partial[t + 256];
    __syncthreads();
    for (int st = 128; st > 0; st >>= 1) {
        if (t < st) red[t] += red[t + st];
        __syncthreads();
    }
    if (t == 0) {
        const double C = -(11.313708498984760390 * 0.69314718055994530942);
        out[0] = (float)(C * (double)red[0]);
    }
}

// ---------------------------------------------------------------------------
extern "C" void kernel_launch(void *const *d_in, const int *in_sizes, int n_in,
                              void *d_out, int out_size) {
    (void)in_sizes; (void)n_in; (void)out_size;
    const float *x  = (const float *)d_in[0];
    const float *Wq = (const float *)d_in[1];
    const float *Wk = (const float *)d_in[2];
    float *out = (float *)d_out;

    static bool attr_set = false;
    if (!attr_set) {
        cudaFuncSetAttribute(proj_kernel, cudaFuncAttributeMaxDynamicSharedMemorySize, 65536);
        cudaFuncSetAttribute(attn_lse_kernel, cudaFuncAttributeMaxDynamicSharedMemorySize, 49152);
        attr_set = true;
    }

    proj_kernel<<<dim3(16, 16, 2), 256, 65536>>>(x, Wq, Wk);
    attn_lse_kernel<<<dim3(16, 32), 128, 49152>>>();
    finalize_kernel<<<1, 256>>>(out);
}

// round 7
// speedup vs baseline: 1.2769x; 1.0891x over previous
#include <cuda_runtime.h>
#include <cuda_bf16.h>
#include <cuda_fp16.h>

// ---------------------------------------------------------------------------
// SelfAttention_50500225466674
// out = -(1/beta) * sum_{h,q} logsumexp_k( beta * (x Wq^T)[q,h,:] . (x Wk^T)[k,h,:] )
// N=2048, D=128, H=32, Z=64, beta = 1/sqrt(128)
// Stage 1: bf16 HMMA projection (R4 config: 1 head/CTA), Q pre-scaled beta*log2e
// Stage 2: fused score GEMM + online base-2 lse. 8 warps: warp pair shares 32
//          q-rows, splits 128 k-cols into two 64-col halves (64 acc regs/thr
//          -> 16 warps/SM). f16x2 epilogue, cp.async double-buffered K tiles.
// Stage 3: deterministic reduction of 512 CTA partials
// ---------------------------------------------------------------------------

#define NTOK 2048
#define DIM  128
#define NH   32
#define ZD   64

static __device__ __nv_bfloat16 g_Q[(size_t)NH * NTOK * ZD];   // 8 MB
static __device__ __nv_bfloat16 g_K[(size_t)NH * NTOK * ZD];   // 8 MB
static __device__ float g_partial[16 * NH];                     // 512 partials

// ---------------- PTX helpers ----------------
__device__ __forceinline__ void ldsm4(unsigned addr, unsigned &r0, unsigned &r1,
                                      unsigned &r2, unsigned &r3) {
    asm volatile("ldmatrix.sync.aligned.m8n8.x4.shared.b16 {%0,%1,%2,%3}, [%4];"
                 : "=r"(r0), "=r"(r1), "=r"(r2), "=r"(r3)
                 : "r"(addr));
}

__device__ __forceinline__ void mma_bf16(float *c, unsigned a0, unsigned a1,
                                         unsigned a2, unsigned a3,
                                         unsigned b0, unsigned b1) {
    asm volatile(
        "mma.sync.aligned.m16n8k16.row.col.f32.bf16.bf16.f32 "
        "{%0,%1,%2,%3}, {%4,%5,%6,%7}, {%8,%9}, {%0,%1,%2,%3};"
        : "+f"(c[0]), "+f"(c[1]), "+f"(c[2]), "+f"(c[3])
        : "r"(a0), "r"(a1), "r"(a2), "r"(a3), "r"(b0), "r"(b1));
}

__device__ __forceinline__ float ex2f(float x) {
    float y; asm("ex2.approx.f32 %0, %1;" : "=f"(y) : "f"(x)); return y;
}
__device__ __forceinline__ float lg2f(float x) {
    float y; asm("lg2.approx.f32 %0, %1;" : "=f"(y) : "f"(x)); return y;
}
__device__ __forceinline__ __half2 h2ex2(__half2 x) {
    unsigned xu = *reinterpret_cast<unsigned *>(&x), yu;
    asm("ex2.approx.f16x2 %0, %1;" : "=r"(yu) : "r"(xu));
    return *reinterpret_cast<__half2 *>(&yu);
}
__device__ __forceinline__ unsigned smem_u32(const void *p) {
    return (unsigned)__cvta_generic_to_shared(p);
}
__device__ __forceinline__ unsigned pack_bf2(float a, float b) {
    __nv_bfloat162 h = __floats2bfloat162_rn(a, b);
    return *reinterpret_cast<unsigned *>(&h);
}
__device__ __forceinline__ void cp16(void *sdst, const void *gsrc) {
    unsigned d = smem_u32(sdst);
    asm volatile("cp.async.cg.shared.global [%0], [%1], 16;" :: "r"(d), "l"(gsrc) : "memory");
}
#define CP_COMMIT() asm volatile("cp.async.commit_group;" ::: "memory")
#define CP_WAIT(n)  asm volatile("cp.async.wait_group %0;" :: "n"(n) : "memory")

// ---------------------------------------------------------------------------
// Stage 1 (R4 config): grid (16 n-tiles, 32 heads, 2 {Q,K}), 256 threads.
// C[128n x 64z] = x_tile[128 x 128] @ W[h]^T. 48KB dynamic smem, XOR swizzle.
// ---------------------------------------------------------------------------
__global__ void __launch_bounds__(256)
proj_kernel(const float *__restrict__ x, const float *__restrict__ Wq,
            const float *__restrict__ Wk) {
    extern __shared__ uint4 smem[];
    uint4 *sX4 = smem;              // 128 rows x 16 chunks(16B)
    uint4 *sW4 = smem + 128 * 16;   // 64 rows x 16 chunks

    const int tid = threadIdx.x, lane = tid & 31, w = tid >> 5;
    const int nb = blockIdx.x * 128, h = blockIdx.y, isK = blockIdx.z;
    const float *W = (isK ? Wk : Wq) + (size_t)h * ZD * DIM;
    __nv_bfloat16 *gout = (isK ? g_K : g_Q) + ((size_t)h * NTOK + nb) * ZD;

    for (int i = tid; i < 2048; i += 256) {
        int row = i >> 4, c = i & 15;
        const float4 *gp =
            reinterpret_cast<const float4 *>(x + (size_t)(nb + row) * DIM + c * 8);
        float4 f0 = gp[0], f1 = gp[1];
        uint4 v;
        v.x = pack_bf2(f0.x, f0.y); v.y = pack_bf2(f0.z, f0.w);
        v.z = pack_bf2(f1.x, f1.y); v.w = pack_bf2(f1.z, f1.w);
        sX4[row * 16 + (c ^ (row & 7))] = v;
    }
    for (int i = tid; i < 1024; i += 256) {
        int row = i >> 4, c = i & 15;
        const float4 *gp =
            reinterpret_cast<const float4 *>(W + (size_t)row * DIM + c * 8);
        float4 f0 = gp[0], f1 = gp[1];
        uint4 v;
        v.x = pack_bf2(f0.x, f0.y); v.y = pack_bf2(f0.z, f0.w);
        v.z = pack_bf2(f1.x, f1.y); v.w = pack_bf2(f1.z, f1.w);
        sW4[row * 16 + (c ^ (row & 7))] = v;
    }
    __syncthreads();

    const int wm = w >> 1, wn = w & 1;   // 4 warps along m(128), 2 along z(64)
    float acc[2][4][4];
#pragma unroll
    for (int i = 0; i < 2; i++)
#pragma unroll
        for (int j = 0; j < 4; j++)
#pragma unroll
            for (int k = 0; k < 4; k++) acc[i][j][k] = 0.f;

    unsigned sXb = smem_u32(sX4), sWb = smem_u32(sW4);
    const int arow0 = wm * 32 + (lane & 15);
    const int brow_off = (lane & 7) + ((lane >> 4) & 1) * 8;
    const int bco = (lane >> 3) & 1;

#pragma unroll
    for (int kk = 0; kk < 8; kk++) {   // K = 128
        unsigned a[2][4];
#pragma unroll
        for (int i = 0; i < 2; i++) {
            int r = arow0 + i * 16;
            int ch = (kk * 2 + (lane >> 4)) ^ (r & 7);
            ldsm4(sXb + (unsigned)((r * 16 + ch) * 16), a[i][0], a[i][1], a[i][2], a[i][3]);
        }
#pragma unroll
        for (int g = 0; g < 2; g++) {
            int brow = wn * 32 + g * 16 + brow_off;
            int bch = (kk * 2 + bco) ^ (brow & 7);
            unsigned b0, b1, b2, b3;
            ldsm4(sWb + (unsigned)((brow * 16 + bch) * 16), b0, b1, b2, b3);
#pragma unroll
            for (int i = 0; i < 2; i++) {
                mma_bf16(acc[i][g * 2],     a[i][0], a[i][1], a[i][2], a[i][3], b0, b1);
                mma_bf16(acc[i][g * 2 + 1], a[i][0], a[i][1], a[i][2], a[i][3], b2, b3);
            }
        }
    }

    const float scale = isK ? 1.0f : (float)(1.4426950408889634 / 11.313708498984760390);

#pragma unroll
    for (int i = 0; i < 2; i++) {
        int r = wm * 32 + i * 16 + (lane >> 2);
#pragma unroll
        for (int j = 0; j < 4; j++) {
            int cb = wn * 32 + j * 8 + 2 * (lane & 3);
            __nv_bfloat162 lo = __floats2bfloat162_rn(acc[i][j][0] * scale, acc[i][j][1] * scale);
            __nv_bfloat162 hi = __floats2bfloat162_rn(acc[i][j][2] * scale, acc[i][j][3] * scale);
            *reinterpret_cast<__nv_bfloat162 *>(gout + (size_t)r * ZD + cb) = lo;
            *reinterpret_cast<__nv_bfloat162 *>(gout + (size_t)(r + 8) * ZD + cb) = hi;
        }
    }
}

// ---------------------------------------------------------------------------
// Stage 2: fused scores + online base-2 lse.
// grid (16 q-tiles, 32 heads), 256 threads (8 warps).
// warp w: row group wr = w&3 (q rows 32*wr..+31), col half wc = w>>2 (64 cols).
// smem (dynamic 48KB): sQ 16KB + sK double-buffer 2x16KB, cp.async pipeline.
// Scores already in base-2 logit units (scale baked into Q by stage 1).
// ---------------------------------------------------------------------------
__global__ void __launch_bounds__(256, 2)
attn_lse_kernel() {
    extern __shared__ uint4 dynsmem[];
    uint4 *sQ4 = dynsmem;            // 128 rows x 8 chunks(16B), swizzled
    uint4 *sK4 = dynsmem + 128 * 8;  // 2 x (128 x 8)
    __shared__ float sM[8][4][8];    // [warp][slice][quad-row]
    __shared__ float sS[8][4][8];
    __shared__ float warpSum[4];

    const int tid = threadIdx.x, lane = tid & 31, w = tid >> 5;
    const int wr = w & 3, wc = w >> 2;
    const int h = blockIdx.y, qt = blockIdx.x;
    const __nv_bfloat16 *gq = g_Q + ((size_t)h * NTOK + (size_t)qt * 128) * ZD;
    const __nv_bfloat16 *gk = g_K + (size_t)h * NTOK * ZD;

    // group 0: Q tile + K tile 0
    for (int i = tid; i < 1024; i += 256) {
        int row = i >> 3, c = i & 7;
        cp16(&sQ4[row * 8 + (c ^ (row & 7))], gq + (size_t)row * ZD + c * 8);
    }
    for (int i = tid; i < 1024; i += 256) {
        int row = i >> 3, c = i & 7;
        cp16(&sK4[row * 8 + (c ^ (row & 7))], gk + (size_t)row * ZD + c * 8);
    }
    CP_COMMIT();

    float m[4], s[4];
#pragma unroll
    for (int i = 0; i < 4; i++) { m[i] = -INFINITY; s[i] = 0.f; }

    const unsigned sQb = smem_u32(sQ4);
    const int brow_off = wc * 64 + (lane & 7) + ((lane >> 4) & 1) * 8;
    const int bco = (lane >> 3) & 1;

#pragma unroll 1
    for (int kt = 0; kt < 16; kt++) {
        if (kt + 1 < 16) {
            const __nv_bfloat16 *gkt = gk + (size_t)(kt + 1) * 128 * ZD;
            uint4 *buf = sK4 + ((kt + 1) & 1) * 1024;
            for (int i = tid; i < 1024; i += 256) {
                int row = i >> 3, c = i & 7;
                cp16(&buf[row * 8 + (c ^ (row & 7))], gkt + (size_t)row * ZD + c * 8);
            }
            CP_COMMIT();
            CP_WAIT(1);
        } else {
            CP_WAIT(0);
        }
        __syncthreads();

        const unsigned sKb = smem_u32(sK4 + (kt & 1) * 1024);
        float acc[2][8][4];
#pragma unroll
        for (int i = 0; i < 2; i++)
#pragma unroll
            for (int j = 0; j < 8; j++)
#pragma unroll
                for (int k = 0; k < 4; k++) acc[i][j][k] = 0.f;

#pragma unroll
        for (int kk = 0; kk < 4; kk++) {   // Z = 64
            unsigned a[2][4];
#pragma unroll
            for (int i = 0; i < 2; i++) {
                int r = 32 * wr + 16 * i + (lane & 15);
                int ch = (kk * 2 + (lane >> 4)) ^ (r & 7);
                ldsm4(sQb + (unsigned)((r * 8 + ch) * 16), a[i][0], a[i][1], a[i][2], a[i][3]);
            }
#pragma unroll
            for (int n16 = 0; n16 < 4; n16++) {
                int brow = n16 * 16 + brow_off;
                int bch = (kk * 2 + bco) ^ (brow & 7);
                unsigned b0, b1, b2, b3;
                ldsm4(sKb + (unsigned)((brow * 8 + bch) * 16), b0, b1, b2, b3);
#pragma unroll
                for (int i = 0; i < 2; i++) {
                    mma_bf16(acc[i][n16 * 2],     a[i][0], a[i][1], a[i][2], a[i][3], b0, b1);
                    mma_bf16(acc[i][n16 * 2 + 1], a[i][0], a[i][1], a[i][2], a[i][3], b2, b3);
                }
            }
        }
        __syncthreads();   // all warps done reading this K buffer

        // f16x2 epilogue: 4 row-slices per thread (i in {0,1}, hh in {0,1})
#pragma unroll
        for (int i = 0; i < 2; i++) {
#pragma unroll
            for (int hh = 0; hh < 2; hh++) {
                const int idx = i * 2 + hh;
                __half2 hv[8];
#pragma unroll
                for (int j = 0; j < 8; j++)
                    hv[j] = __floats2half2_rn(acc[i][j][2 * hh], acc[i][j][2 * hh + 1]);
                __half2 mx[4];
#pragma unroll
                for (int j = 0; j < 4; j++) mx[j] = __hmax2(hv[j], hv[j + 4]);
                mx[0] = __hmax2(__hmax2(mx[0], mx[1]), __hmax2(mx[2], mx[3]));
                float tmax = fmaxf(__low2float(mx[0]), __high2float(mx[0]));

                float mn = fmaxf(m[idx], tmax);
                s[idx] *= ex2f(m[idx] - mn);
                m[idx] = mn;
                __half2 mn2 = __float2half2_rn(mn);
                __half2 a0 = __float2half2_rn(0.f), a1 = a0, a2 = a0, a3 = a0;
                a0 = h2ex2(__hsub2(hv[0], mn2));
                a1 = h2ex2(__hsub2(hv[1], mn2));
                a2 = h2ex2(__hsub2(hv[2], mn2));
                a3 = h2ex2(__hsub2(hv[3], mn2));
                a0 = __hadd2(a0, h2ex2(__hsub2(hv[4], mn2)));
                a1 = __hadd2(a1, h2ex2(__hsub2(hv[5], mn2)));
                a2 = __hadd2(a2, h2ex2(__hsub2(hv[6], mn2)));
                a3 = __hadd2(a3, h2ex2(__hsub2(hv[7], mn2)));
                a0 = __hadd2(__hadd2(a0, a1), __hadd2(a2, a3));
                s[idx] += __low2float(a0) + __high2float(a0);
            }
        }
    }

    // merge (m,s) across the 4 lanes of each quad (each slice = 64-col half row)
#pragma unroll
    for (int idx = 0; idx < 4; idx++) {
        float mm = m[idx], ss = s[idx];
#pragma unroll
        for (int off = 1; off <= 2; off <<= 1) {
            float mo = __shfl_xor_sync(0xffffffffu, mm, off);
            float so = __shfl_xor_sync(0xffffffffu, ss, off);
            float mn = fmaxf(mm, mo);
            ss = ss * ex2f(mm - mn) + so * ex2f(mo - mn);
            mm = mn;
        }
        m[idx] = mm; s[idx] = ss;
    }
    if ((lane & 3) == 0) {
#pragma unroll
        for (int idx = 0; idx < 4; idx++) {
            sM[w][idx][lane >> 2] = m[idx];
            sS[w][idx][lane >> 2] = s[idx];
        }
    }
    __syncthreads();

    // warps 0-3: merge col-half partner (w+4), per-row lse, warp-sum
    float contrib = 0.f;
    if (wc == 0 && (lane & 3) == 0) {
#pragma unroll
        for (int idx = 0; idx < 4; idx++) {
            float ma = sM[w][idx][lane >> 2], sa = sS[w][idx][lane >> 2];
            float mb = sM[w + 4][idx][lane >> 2], sb = sS[w + 4][idx][lane >> 2];
            float mn = fmaxf(ma, mb);
            float ss = sa * ex2f(ma - mn) + sb * ex2f(mb - mn);
            contrib += mn + lg2f(ss);
        }
    }
    if (wc == 0) {
#pragma unroll
        for (int off = 16; off; off >>= 1)
            contrib += __shfl_xor_sync(0xffffffffu, contrib, off);
        if (lane == 0) warpSum[wr] = contrib;
    }
    __syncthreads();
    if (tid == 0)
        g_partial[blockIdx.y * 16 + blockIdx.x] =
            warpSum[0] + warpSum[1] + warpSum[2] + warpSum[3];
}

// ---------------------------------------------------------------------------
// Stage 3: deterministic reduction; out = -sqrt(128)*ln2 * sum(base-2 lse)
// ---------------------------------------------------------------------------
__global__ void finalize_kernel(float *out) {
    __shared__ float red[256];
    int t = threadIdx.x;
    red[t] = g_partial[t] + g_partial[t + 256];
    __syncthreads();
    for (int st = 128; st > 0; st >>= 1) {
        if (t < st) red[t] += red[t + st];
        __syncthreads();
    }
    if (t == 0) {
        const double C = -(11.313708498984760390 * 0.69314718055994530942);
        out[0] = (float)(C * (double)red[0]);
    }
}

// ---------------------------------------------------------------------------
extern "C" void kernel_launch(void *const *d_in, const int *in_sizes, int n_in,
                              void *d_out, int out_size) {
    (void)in_sizes; (void)n_in; (void)out_size;
    const float *x  = (const float *)d_in[0];
    const float *Wq = (const float *)d_in[1];
    const float *Wk = (const float *)d_in[2];
    float *out = (float *)d_out;

    static bool attr_set = false;
    if (!attr_set) {
        cudaFuncSetAttribute(proj_kernel, cudaFuncAttributeMaxDynamicSharedMemorySize, 49152);
        cudaFuncSetAttribute(attn_lse_kernel, cudaFuncAttributeMaxDynamicSharedMemorySize, 49152);
        attr_set = true;
    }

    proj_kernel<<<dim3(16, 32, 2), 256, 49152>>>(x, Wq, Wk);
    attn_lse_kernel<<<dim3(16, 32), 256, 49152>>>();
    finalize_kernel<<<1, 256>>>(out);
}

// round 8
// speedup vs baseline: 1.3892x; 1.0879x over previous
#include <cuda_runtime.h>
#include <cuda_bf16.h>
#include <cuda_fp16.h>

// ---------------------------------------------------------------------------
// SelfAttention_50500225466674
// out = -(1/beta) * sum_{h,q} logsumexp_k( beta * (x Wq^T)[q,h,:] . (x Wk^T)[k,h,:] )
// N=2048, D=128, H=32, Z=64, beta = 1/sqrt(128)
// Stage 0: fp32 -> fp16 conversion of x, Wq, Wk (once)
// Stage 1: fp16 HMMA projection (f32 acc), sqrt(beta*log2e) folded into BOTH
//          Q and K -> scores come out of stage 2 directly as base-2 logits
// Stage 2: fused score GEMM with f16 accumulators + online base-2 lse.
//          8 warps (4 row-groups x 2 col-halves), Q frags register-resident,
//          epilogue fused into the MMA barrier window, cp.async double buffer
// Stage 3: deterministic reduction of 512 CTA partials
// ---------------------------------------------------------------------------

#define NTOK 2048
#define DIM  128
#define NH   32
#define ZD   64

static __device__ __half g_x16[(size_t)NTOK * DIM];            // 0.5 MB
static __device__ __half g_W16[(size_t)2 * NH * ZD * DIM];     // 1 MB (Wq|Wk)
static __device__ __half g_Q[(size_t)NH * NTOK * ZD];          // 8 MB
static __device__ __half g_K[(size_t)NH * NTOK * ZD];          // 8 MB
static __device__ float g_partial[16 * NH];                    // 512 partials

// sqrt(log2(e)/sqrt(128)) : folded into both Q and K
#define QK_SCALE 0.3570959f

// ---------------- PTX helpers ----------------
__device__ __forceinline__ void ldsm4(unsigned addr, unsigned &r0, unsigned &r1,
                                      unsigned &r2, unsigned &r3) {
    asm volatile("ldmatrix.sync.aligned.m8n8.x4.shared.b16 {%0,%1,%2,%3}, [%4];"
                 : "=r"(r0), "=r"(r1), "=r"(r2), "=r"(r3)
                 : "r"(addr));
}

// f16 inputs, f32 accumulators (projection)
__device__ __forceinline__ void mma_f16_f32(float *c, unsigned a0, unsigned a1,
                                            unsigned a2, unsigned a3,
                                            unsigned b0, unsigned b1) {
    asm volatile(
        "mma.sync.aligned.m16n8k16.row.col.f32.f16.f16.f32 "
        "{%0,%1,%2,%3}, {%4,%5,%6,%7}, {%8,%9}, {%0,%1,%2,%3};"
        : "+f"(c[0]), "+f"(c[1]), "+f"(c[2]), "+f"(c[3])
        : "r"(a0), "r"(a1), "r"(a2), "r"(a3), "r"(b0), "r"(b1));
}

// f16 inputs, f16 accumulators (scores)
__device__ __forceinline__ void mma_f16_f16(unsigned &c0, unsigned &c1,
                                            unsigned a0, unsigned a1,
                                            unsigned a2, unsigned a3,
                                            unsigned b0, unsigned b1) {
    asm volatile(
        "mma.sync.aligned.m16n8k16.row.col.f16.f16.f16.f16 "
        "{%0,%1}, {%2,%3,%4,%5}, {%6,%7}, {%0,%1};"
        : "+r"(c0), "+r"(c1)
        : "r"(a0), "r"(a1), "r"(a2), "r"(a3), "r"(b0), "r"(b1));
}

__device__ __forceinline__ float ex2f(float x) {
    float y; asm("ex2.approx.f32 %0, %1;" : "=f"(y) : "f"(x)); return y;
}
__device__ __forceinline__ float lg2f(float x) {
    float y; asm("lg2.approx.f32 %0, %1;" : "=f"(y) : "f"(x)); return y;
}
__device__ __forceinline__ __half2 h2ex2(__half2 x) {
    unsigned xu = *reinterpret_cast<unsigned *>(&x), yu;
    asm("ex2.approx.f16x2 %0, %1;" : "=r"(yu) : "r"(xu));
    return *reinterpret_cast<__half2 *>(&yu);
}
__device__ __forceinline__ __half2 u2h(unsigned u) {
    return *reinterpret_cast<__half2 *>(&u);
}
__device__ __forceinline__ unsigned smem_u32(const void *p) {
    return (unsigned)__cvta_generic_to_shared(p);
}
__device__ __forceinline__ void cp16(void *sdst, const void *gsrc) {
    unsigned d = smem_u32(sdst);
    asm volatile("cp.async.cg.shared.global [%0], [%1], 16;" :: "r"(d), "l"(gsrc) : "memory");
}
#define CP_COMMIT() asm volatile("cp.async.commit_group;" ::: "memory")
#define CP_WAIT(n)  asm volatile("cp.async.wait_group %0;" :: "n"(n) : "memory")

// ---------------------------------------------------------------------------
// Stage 0: fp32 -> fp16 for x, Wq, Wk.  393216 float2 -> half2.
// layout: idx [0,128K) = x ; [128K,256K) = Wq ; [256K,384K) = Wk
// ---------------------------------------------------------------------------
__global__ void __launch_bounds__(256)
prep_kernel(const float *__restrict__ x, const float *__restrict__ Wq,
            const float *__restrict__ Wk) {
    int idx = blockIdx.x * 256 + threadIdx.x;   // 0..393215
    float2 v;
    __half2 *dst;
    if (idx < 131072) {
        v = reinterpret_cast<const float2 *>(x)[idx];
        dst = reinterpret_cast<__half2 *>(g_x16) + idx;
    } else if (idx < 262144) {
        v = reinterpret_cast<const float2 *>(Wq)[idx - 131072];
        dst = reinterpret_cast<__half2 *>(g_W16) + (idx - 131072);
    } else {
        v = reinterpret_cast<const float2 *>(Wk)[idx - 262144];
        dst = reinterpret_cast<__half2 *>(g_W16) + (idx - 131072);
    }
    *dst = __floats2half2_rn(v.x, v.y);
}

// ---------------------------------------------------------------------------
// Stage 1: projection. grid (16 n-tiles, 32 heads, 2 {Q,K}), 256 threads.
// C[128n x 64z] = x16_tile[128x128] @ W16[h]^T, f16 in / f32 acc.
// smem 48KB dynamic: sX 32KB + sW 16KB, XOR swizzle, cp.async loads.
// Output scaled by QK_SCALE (both Q and K) and stored fp16.
// ---------------------------------------------------------------------------
__global__ void __launch_bounds__(256)
proj_kernel() {
    extern __shared__ uint4 smem[];
    uint4 *sX4 = smem;              // 128 rows x 16 chunks(16B)
    uint4 *sW4 = smem + 128 * 16;   // 64 rows x 16 chunks

    const int tid = threadIdx.x, lane = tid & 31, w = tid >> 5;
    const int nb = blockIdx.x * 128, h = blockIdx.y, isK = blockIdx.z;
    const __half *X = g_x16 + (size_t)nb * DIM;
    const __half *W = g_W16 + (size_t)isK * NH * ZD * DIM + (size_t)h * ZD * DIM;
    __half *gout = (isK ? g_K : g_Q) + ((size_t)h * NTOK + nb) * ZD;

    for (int i = tid; i < 2048; i += 256) {          // x tile: 128 x 16 chunks
        int row = i >> 4, c = i & 15;
        cp16(&sX4[row * 16 + (c ^ (row & 7))], X + (size_t)row * DIM + c * 8);
    }
    for (int i = tid; i < 1024; i += 256) {          // W tile: 64 x 16 chunks
        int row = i >> 4, c = i & 15;
        cp16(&sW4[row * 16 + (c ^ (row & 7))], W + (size_t)row * DIM + c * 8);
    }
    CP_COMMIT();
    CP_WAIT(0);
    __syncthreads();

    const int wm = w >> 1, wn = w & 1;   // 4 warps along m(128), 2 along z(64)
    float acc[2][4][4];
#pragma unroll
    for (int i = 0; i < 2; i++)
#pragma unroll
        for (int j = 0; j < 4; j++)
#pragma unroll
            for (int k = 0; k < 4; k++) acc[i][j][k] = 0.f;

    unsigned sXb = smem_u32(sX4), sWb = smem_u32(sW4);
    const int arow0 = wm * 32 + (lane & 15);
    const int brow_off = (lane & 7) + ((lane >> 4) & 1) * 8;
    const int bco = (lane >> 3) & 1;

#pragma unroll
    for (int kk = 0; kk < 8; kk++) {   // K = 128
        unsigned a[2][4];
#pragma unroll
        for (int i = 0; i < 2; i++) {
            int r = arow0 + i * 16;
            int ch = (kk * 2 + (lane >> 4)) ^ (r & 7);
            ldsm4(sXb + (unsigned)((r * 16 + ch) * 16), a[i][0], a[i][1], a[i][2], a[i][3]);
        }
#pragma unroll
        for (int g = 0; g < 2; g++) {
            int brow = wn * 32 + g * 16 + brow_off;
            int bch = (kk * 2 + bco) ^ (brow & 7);
            unsigned b0, b1, b2, b3;
            ldsm4(sWb + (unsigned)((brow * 16 + bch) * 16), b0, b1, b2, b3);
#pragma unroll
            for (int i = 0; i < 2; i++) {
                mma_f16_f32(acc[i][g * 2],     a[i][0], a[i][1], a[i][2], a[i][3], b0, b1);
                mma_f16_f32(acc[i][g * 2 + 1], a[i][0], a[i][1], a[i][2], a[i][3], b2, b3);
            }
        }
    }

#pragma unroll
    for (int i = 0; i < 2; i++) {
        int r = wm * 32 + i * 16 + (lane >> 2);
#pragma unroll
        for (int j = 0; j < 4; j++) {
            int cb = wn * 32 + j * 8 + 2 * (lane & 3);
            __half2 lo = __floats2half2_rn(acc[i][j][0] * QK_SCALE, acc[i][j][1] * QK_SCALE);
            __half2 hi = __floats2half2_rn(acc[i][j][2] * QK_SCALE, acc[i][j][3] * QK_SCALE);
            *reinterpret_cast<__half2 *>(gout + (size_t)r * ZD + cb) = lo;
            *reinterpret_cast<__half2 *>(gout + (size_t)(r + 8) * ZD + cb) = hi;
        }
    }
}

// ---------------------------------------------------------------------------
// Stage 2 epilogue step: online (m, s) update from one f16-acc bank.
// bank[i][j][hh] : i = 16-row block, j = 8-col n-tile (j<8 -> 64 cols),
// hh = row offset (0 / +8). Each (i,hh) slice = 16 scores of ONE q row.
// ---------------------------------------------------------------------------
__device__ __forceinline__ void epi_bank(unsigned (&bank)[2][8][2],
                                         float *m, float *s) {
#pragma unroll
    for (int i = 0; i < 2; i++) {
#pragma unroll
        for (int hh = 0; hh < 2; hh++) {
            const int idx = i * 2 + hh;
            __half2 hv[8];
#pragma unroll
            for (int j = 0; j < 8; j++) hv[j] = u2h(bank[i][j][hh]);
            __half2 mx0 = __hmax2(hv[0], hv[4]);
            __half2 mx1 = __hmax2(hv[1], hv[5]);
            __half2 mx2 = __hmax2(hv[2], hv[6]);
            __half2 mx3 = __hmax2(hv[3], hv[7]);
            mx0 = __hmax2(__hmax2(mx0, mx1), __hmax2(mx2, mx3));
            float tmax = fmaxf(__low2float(mx0), __high2float(mx0));

            float mn = fmaxf(m[idx], tmax);
            s[idx] *= ex2f(m[idx] - mn);
            m[idx] = mn;
            __half2 mn2 = __float2half2_rn(mn);
            __half2 a0 = h2ex2(__hsub2(hv[0], mn2));
            __half2 a1 = h2ex2(__hsub2(hv[1], mn2));
            __half2 a2 = h2ex2(__hsub2(hv[2], mn2));
            __half2 a3 = h2ex2(__hsub2(hv[3], mn2));
            a0 = __hadd2(a0, h2ex2(__hsub2(hv[4], mn2)));
            a1 = __hadd2(a1, h2ex2(__hsub2(hv[5], mn2)));
            a2 = __hadd2(a2, h2ex2(__hsub2(hv[6], mn2)));
            a3 = __hadd2(a3, h2ex2(__hsub2(hv[7], mn2)));
            a0 = __hadd2(__hadd2(a0, a1), __hadd2(a2, a3));
            s[idx] += __low2float(a0) + __high2float(a0);
        }
    }
}

// ---------------------------------------------------------------------------
// Stage 2: fused scores + online base-2 lse.
// grid (16 q-tiles, 32 heads), 256 threads (8 warps).
// warp w: rows 32*(w&3)..+31, col half (w>>2)*64..+63. f16 accumulators.
// Q fragments register-resident for all 16 K tiles. Epilogue fused into the
// MMA barrier window. cp.async double-buffered K tiles (48KB dynamic smem).
// ---------------------------------------------------------------------------
__global__ void __launch_bounds__(256, 2)
attn_lse_kernel() {
    extern __shared__ uint4 dynsmem[];
    uint4 *sQ4 = dynsmem;            // 128 rows x 8 chunks(16B), swizzled
    uint4 *sK4 = dynsmem + 128 * 8;  // 2 x (128 x 8)
    __shared__ float sM[8][4][8];    // [warp][slice][quad-row]
    __shared__ float sS[8][4][8];
    __shared__ float warpSum[4];

    const int tid = threadIdx.x, lane = tid & 31, w = tid >> 5;
    const int wr = w & 3, wc = w >> 2;
    const int h = blockIdx.y, qt = blockIdx.x;
    const __half *gq = g_Q + ((size_t)h * NTOK + (size_t)qt * 128) * ZD;
    const __half *gk = g_K + (size_t)h * NTOK * ZD;

    // group 0: Q + K0 ; group 1: K1
    for (int i = tid; i < 1024; i += 256) {
        int row = i >> 3, c = i & 7;
        cp16(&sQ4[row * 8 + (c ^ (row & 7))], gq + (size_t)row * ZD + c * 8);
    }
    for (int i = tid; i < 1024; i += 256) {
        int row = i >> 3, c = i & 7;
        cp16(&sK4[row * 8 + (c ^ (row & 7))], gk + (size_t)row * ZD + c * 8);
    }
    CP_COMMIT();
    {
        const __half *gk1 = gk + (size_t)128 * ZD;
        uint4 *buf = sK4 + 1024;
        for (int i = tid; i < 1024; i += 256) {
            int row = i >> 3, c = i & 7;
            cp16(&buf[row * 8 + (c ^ (row & 7))], gk1 + (size_t)row * ZD + c * 8);
        }
        CP_COMMIT();
    }
    CP_WAIT(1);          // Q + K0 ready
    __syncthreads();

    // Q fragments register-resident: aq[kk][i][0..3]
    unsigned aq[4][2][4];
    {
        const unsigned sQb = smem_u32(sQ4);
#pragma unroll
        for (int kk = 0; kk < 4; kk++)
#pragma unroll
            for (int i = 0; i < 2; i++) {
                int r = 32 * wr + 16 * i + (lane & 15);
                int ch = (kk * 2 + (lane >> 4)) ^ (r & 7);
                ldsm4(sQb + (unsigned)((r * 8 + ch) * 16),
                      aq[kk][i][0], aq[kk][i][1], aq[kk][i][2], aq[kk][i][3]);
            }
    }

    float m[4], s[4];
#pragma unroll
    for (int i = 0; i < 4; i++) { m[i] = -INFINITY; s[i] = 0.f; }

    unsigned bank[2][8][2];
#pragma unroll
    for (int i = 0; i < 2; i++)
#pragma unroll
        for (int j = 0; j < 8; j++) { bank[i][j][0] = 0u; bank[i][j][1] = 0u; }

    const int brow_off = wc * 64 + (lane & 7) + ((lane >> 4) & 1) * 8;
    const int bco = (lane >> 3) & 1;

#pragma unroll 1
    for (int kt = 0; kt < 16; kt++) {
        const unsigned sKb = smem_u32(sK4 + (kt & 1) * 1024);

        // ---- MMA(tile kt) + epilogue fused in one barrier-free window ----
#pragma unroll
        for (int kk = 0; kk < 4; kk++) {
#pragma unroll
            for (int n16 = 0; n16 < 4; n16++) {
                int brow = n16 * 16 + brow_off;
                int bch = (kk * 2 + bco) ^ (brow & 7);
                unsigned b0, b1, b2, b3;
                ldsm4(sKb + (unsigned)((brow * 8 + bch) * 16), b0, b1, b2, b3);
#pragma unroll
                for (int i = 0; i < 2; i++) {
                    mma_f16_f16(bank[i][n16 * 2][0],     bank[i][n16 * 2][1],
                                aq[kk][i][0], aq[kk][i][1], aq[kk][i][2], aq[kk][i][3],
                                b0, b1);
                    mma_f16_f16(bank[i][n16 * 2 + 1][0], bank[i][n16 * 2 + 1][1],
                                aq[kk][i][0], aq[kk][i][1], aq[kk][i][2], aq[kk][i][3],
                                b2, b3);
                }
            }
        }
        epi_bank(bank, m, s);
#pragma unroll
        for (int i = 0; i < 2; i++)
#pragma unroll
            for (int j = 0; j < 8; j++) { bank[i][j][0] = 0u; bank[i][j][1] = 0u; }

        __syncthreads();   // all warps done reading buf[kt&1]

        if (kt + 2 < 16) {
            const __half *gkt = gk + (size_t)(kt + 2) * 128 * ZD;
            uint4 *buf = sK4 + (kt & 1) * 1024;
            for (int i = tid; i < 1024; i += 256) {
                int row = i >> 3, c = i & 7;
                cp16(&buf[row * 8 + (c ^ (row & 7))], gkt + (size_t)row * ZD + c * 8);
            }
            CP_COMMIT();
            CP_WAIT(1);    // K(kt+1) done (FIFO)
        } else if (kt + 1 < 16) {
            CP_WAIT(0);    // drain K15
        }
        __syncthreads();
    }

    // merge (m,s) across the 4 lanes of each quad (slice = 64-col half row)
#pragma unroll
    for (int idx = 0; idx < 4; idx++) {
        float mm = m[idx], ss = s[idx];
#pragma unroll
        for (int off = 1; off <= 2; off <<= 1) {
            float mo = __shfl_xor_sync(0xffffffffu, mm, off);
            float so = __shfl_xor_sync(0xffffffffu, ss, off);
            float mn = fmaxf(mm, mo);
            ss = ss * ex2f(mm - mn) + so * ex2f(mo - mn);
            mm = mn;
        }
        m[idx] = mm; s[idx] = ss;
    }
    if ((lane & 3) == 0) {
#pragma unroll
        for (int idx = 0; idx < 4; idx++) {
            sM[w][idx][lane >> 2] = m[idx];
            sS[w][idx][lane >> 2] = s[idx];
        }
    }
    __syncthreads();

    // warps 0-3: merge col-half partner (w+4), per-row lse, warp-sum
    float contrib = 0.f;
    if (wc == 0 && (lane & 3) == 0) {
#pragma unroll
        for (int idx = 0; idx < 4; idx++) {
            float ma = sM[w][idx][lane >> 2], sa = sS[w][idx][lane >> 2];
            float mb = sM[w + 4][idx][lane >> 2], sb = sS[w + 4][idx][lane >> 2];
            float mn = fmaxf(ma, mb);
            float ss = sa * ex2f(ma - mn) + sb * ex2f(mb - mn);
            contrib += mn + lg2f(ss);
        }
    }
    if (wc == 0) {
#pragma unroll
        for (int off = 16; off; off >>= 1)
            contrib += __shfl_xor_sync(0xffffffffu, contrib, off);
        if (lane == 0) warpSum[wr] = contrib;
    }
    __syncthreads();
    if (tid == 0)
        g_partial[blockIdx.y * 16 + blockIdx.x] =
            warpSum[0] + warpSum[1] + warpSum[2] + warpSum[3];
}

// ---------------------------------------------------------------------------
// Stage 3: deterministic reduction; out = -sqrt(128)*ln2 * sum(base-2 lse)
// ---------------------------------------------------------------------------
__global__ void finalize_kernel(float *out) {
    __shared__ float red[256];
    int t = threadIdx.x;
    red[t] = g_partial[t] + g_partial[t + 256];
    __syncthreads();
    for (int st = 128; st > 0; st >>= 1) {
        if (t < st) red[t] += red[t + st];
        __syncthreads();
    }
    if (t == 0) {
        const double C = -(11.313708498984760390 * 0.69314718055994530942);
        out[0] = (float)(C * (double)red[0]);
    }
}

// ---------------------------------------------------------------------------
extern "C" void kernel_launch(void *const *d_in, const int *in_sizes, int n_in,
                              void *d_out, int out_size) {
    (void)in_sizes; (void)n_in; (void)out_size;
    const float *x  = (const float *)d_in[0];
    const float *Wq = (const float *)d_in[1];
    const float *Wk = (const float *)d_in[2];
    float *out = (float *)d_out;

    static bool attr_set = false;
    if (!attr_set) {
        cudaFuncSetAttribute(proj_kernel, cudaFuncAttributeMaxDynamicSharedMemorySize, 49152);
        cudaFuncSetAttribute(attn_lse_kernel, cudaFuncAttributeMaxDynamicSharedMemorySize, 49152);
        attr_set = true;
    }

    prep_kernel<<<1536, 256>>>(x, Wq, Wk);
    proj_kernel<<<dim3(16, 32, 2), 256, 49152>>>();
    attn_lse_kernel<<<dim3(16, 32), 256, 49152>>>();
    finalize_kernel<<<1, 256>>>(out);
}